// round 2
// baseline (speedup 1.0000x reference)
#include <cuda_runtime.h>

#define N_NODES 100000
#define F_IN    128
#define HDIM    64
#define CDIM    40
#define E_MAX   1600000

// ---- scratch (device globals) ----
__device__ __align__(256) float g_dinv [N_NODES];
__device__ __align__(256) int   g_count[N_NODES];
__device__ __align__(256) int   g_start[N_NODES];
__device__ __align__(256) int   g_cursor[N_NODES];
__device__ __align__(256) int   g_srcs [E_MAX];
__device__ __align__(256) float g_h1s  [N_NODES * HDIM];   // (x@W1)*dinv[row]
__device__ __align__(256) float g_agg1 [N_NODES * HDIM];   // self + neighbors
__device__ __align__(256) float g_h2s  [N_NODES * CDIM];   // (relu(..)@W2)*dinv

// ---- packed f32x2 helpers ----
__device__ __forceinline__ unsigned long long pack2(float x) {
    unsigned long long r;
    asm("mov.b64 %0, {%1, %1};" : "=l"(r) : "f"(x));
    return r;
}
__device__ __forceinline__ void fma2(unsigned long long& d,
                                     unsigned long long a, unsigned long long b) {
    asm("fma.rn.f32x2 %0, %1, %2, %3;" : "=l"(d) : "l"(a), "l"(b), "l"(d));
}
__device__ __forceinline__ float2 unpack2(unsigned long long v) {
    float2 f;
    asm("mov.b64 {%0, %1}, %2;" : "=f"(f.x), "=f"(f.y) : "l"(v));
    return f;
}

// ------------------------------------------------------------- CSR build ----
__global__ void k_zero() {
    int i = blockIdx.x * blockDim.x + threadIdx.x;
    if (i < N_NODES) g_count[i] = 0;
}

__global__ void k_count(const int* __restrict__ ei, int E) {
    int e = blockIdx.x * blockDim.x + threadIdx.x;
    if (e >= E) return;
    int d = ei[E + e];
    if ((unsigned)d < (unsigned)N_NODES) atomicAdd(&g_count[d], 1);
}

// single block, 1024 threads: exclusive scan + dinv
__global__ void k_scan() {
    const int T = 1024;
    const int CH = (N_NODES + T - 1) / T;
    int t = threadIdx.x;
    int beg = t * CH;
    int end = min(beg + CH, N_NODES);
    int sum = 0;
    for (int i = beg; i < end; i++) sum += g_count[i];

    int lane = t & 31, wid = t >> 5;
    int v = sum;
    #pragma unroll
    for (int o = 1; o < 32; o <<= 1) {
        int u = __shfl_up_sync(0xFFFFFFFFu, v, o);
        if (lane >= o) v += u;
    }
    __shared__ int ws[32];
    if (lane == 31) ws[wid] = v;
    __syncthreads();
    if (wid == 0) {
        int w = ws[lane];
        #pragma unroll
        for (int o = 1; o < 32; o <<= 1) {
            int u = __shfl_up_sync(0xFFFFFFFFu, w, o);
            if (lane >= o) w += u;
        }
        ws[lane] = w;
    }
    __syncthreads();
    int off = v - sum + (wid ? ws[wid - 1] : 0);   // exclusive prefix
    for (int i = beg; i < end; i++) {
        g_start[i] = off;
        g_cursor[i] = off;
        int c = g_count[i];
        g_dinv[i] = rsqrtf(1.0f + (float)c);
        off += c;
    }
}

__global__ void k_place(const int* __restrict__ ei, int E) {
    int e = blockIdx.x * blockDim.x + threadIdx.x;
    if (e >= E) return;
    int s = ei[e], d = ei[E + e];
    if ((unsigned)s >= (unsigned)N_NODES || (unsigned)d >= (unsigned)N_NODES) return;
    int pos = atomicAdd(&g_cursor[d], 1);
    if (pos < E_MAX) g_srcs[pos] = s;
}

// ------------------------------------------------ GEMM1: h1s = (x@W1)*dinv ----
// block 256 thr, tile 128 rows x 64 cols; thread: 4 rows x 8 cols (f32x2 x4)
__global__ __launch_bounds__(256, 2) void k_gemm1(const float* __restrict__ x,
                                                  const float* __restrict__ W1) {
    __shared__ float Ws[32 * 64];        // 8 KB
    __shared__ float Xs[128 * 33];       // 16.9 KB (pad 33: conflict-free)

    const int tid = threadIdx.x;
    const int cg  = tid & 7;             // cols cg*8 .. cg*8+7
    const int rg  = tid >> 3;            // rows rg*4 .. rg*4+3
    const int rowBase = blockIdx.x * 128;

    unsigned long long acc[4][4];
    #pragma unroll
    for (int r = 0; r < 4; r++)
        #pragma unroll
        for (int c = 0; c < 4; c++) acc[r][c] = 0ull;

    for (int k0 = 0; k0 < F_IN; k0 += 32) {
        // stage W chunk [32][64]: 8 floats per thread (two float4)
        {
            int r = tid >> 3, c = (tid & 7) * 8;
            float4 a = *(const float4*)&W1[(k0 + r) * HDIM + c];
            float4 b = *(const float4*)&W1[(k0 + r) * HDIM + c + 4];
            *(float4*)&Ws[r * 64 + c]     = a;
            *(float4*)&Ws[r * 64 + c + 4] = b;
        }
        // stage X chunk [128][32], pad 33: 16 floats per thread
        {
            int r = tid >> 1, kk = (tid & 1) * 16;
            int row = rowBase + r;
            if (row < N_NODES) {
                const float* xp = &x[(long long)row * F_IN + k0 + kk];
                float4 a = *(const float4*)(xp);
                float4 b = *(const float4*)(xp + 4);
                float4 c = *(const float4*)(xp + 8);
                float4 d = *(const float4*)(xp + 12);
                float* s = &Xs[r * 33 + kk];
                s[0]=a.x; s[1]=a.y; s[2]=a.z; s[3]=a.w;
                s[4]=b.x; s[5]=b.y; s[6]=b.z; s[7]=b.w;
                s[8]=c.x; s[9]=c.y; s[10]=c.z; s[11]=c.w;
                s[12]=d.x; s[13]=d.y; s[14]=d.z; s[15]=d.w;
            } else {
                float* s = &Xs[r * 33 + kk];
                #pragma unroll
                for (int i = 0; i < 16; i++) s[i] = 0.f;
            }
        }
        __syncthreads();
        #pragma unroll
        for (int k = 0; k < 32; k++) {
            ulonglong2 wa = *(const ulonglong2*)&Ws[k * 64 + cg * 8];
            ulonglong2 wb = *(const ulonglong2*)&Ws[k * 64 + cg * 8 + 4];
            #pragma unroll
            for (int r = 0; r < 4; r++) {
                unsigned long long xp = pack2(Xs[(rg * 4 + r) * 33 + k]);
                fma2(acc[r][0], xp, wa.x);
                fma2(acc[r][1], xp, wa.y);
                fma2(acc[r][2], xp, wb.x);
                fma2(acc[r][3], xp, wb.y);
            }
        }
        __syncthreads();
    }

    #pragma unroll
    for (int r = 0; r < 4; r++) {
        int row = rowBase + rg * 4 + r;
        if (row < N_NODES) {
            float s = g_dinv[row];
            float2 p0 = unpack2(acc[r][0]), p1 = unpack2(acc[r][1]);
            float2 p2 = unpack2(acc[r][2]), p3 = unpack2(acc[r][3]);
            float4 o0 = make_float4(p0.x*s, p0.y*s, p1.x*s, p1.y*s);
            float4 o1 = make_float4(p2.x*s, p2.y*s, p3.x*s, p3.y*s);
            float* dst = &g_h1s[(long long)row * HDIM + cg * 8];
            *(float4*)(dst)     = o0;
            *(float4*)(dst + 4) = o1;
        }
    }
}

// -------------------------------------- agg1: warp per node, register accumulate
__global__ __launch_bounds__(256) void k_agg1() {
    int warp = (blockIdx.x * blockDim.x + threadIdx.x) >> 5;
    if (warp >= N_NODES) return;
    int lane = threadIdx.x & 31;
    int start = g_start[warp];
    int cnt   = g_count[warp];

    float2 acc = *(const float2*)&g_h1s[(long long)warp * HDIM + lane * 2]; // self loop
    for (int b = 0; b < cnt; b += 32) {
        int nb = min(32, cnt - b);
        int s = (b + lane < cnt) ? g_srcs[start + b + lane] : 0;
        #pragma unroll 4
        for (int j = 0; j < nb; j++) {
            int sj = __shfl_sync(0xFFFFFFFFu, s, j);
            float2 v = *(const float2*)&g_h1s[(long long)sj * HDIM + lane * 2];
            acc.x += v.x; acc.y += v.y;
        }
    }
    *(float2*)&g_agg1[(long long)warp * HDIM + lane * 2] = acc;
}

// ------------------ GEMM2: h2s = relu(dinv*agg1 + b1) @ W2 * dinv  (f32x2) ----
// block 320 thr, tile 128 rows x 40 cols; thread: 4 rows x 4 cols (2 f32x2)
__global__ __launch_bounds__(320) void k_gemm2(const float* __restrict__ W2,
                                               const float* __restrict__ b1) {
    __shared__ float Ws[64 * 40];        // 10.2 KB
    __shared__ float Xs[128 * 65];       // 33.3 KB (pad 65)
    __shared__ float Bs[64];

    const int tid = threadIdx.x;
    const int cg  = tid % 10;            // cols cg*4 .. cg*4+3
    const int rg  = tid / 10;            // rows rg*4 .. rg*4+3
    const int rowBase = blockIdx.x * 128;

    for (int i = tid; i < 64 * 40; i += 320) Ws[i] = W2[i];
    if (tid < 64) Bs[tid] = b1[tid];
    __syncthreads();

    for (int i = tid; i < 128 * 64; i += 320) {
        int r = i >> 6, k = i & 63;
        int row = rowBase + r;
        float v = 0.f;
        if (row < N_NODES)
            v = fmaxf(g_dinv[row] * g_agg1[(long long)row * HDIM + k] + Bs[k], 0.f);
        Xs[r * 65 + k] = v;
    }
    __syncthreads();

    unsigned long long acc[4][2];
    #pragma unroll
    for (int r = 0; r < 4; r++) { acc[r][0] = 0ull; acc[r][1] = 0ull; }

    #pragma unroll 4
    for (int k = 0; k < 64; k++) {
        ulonglong2 w = *(const ulonglong2*)&Ws[k * 40 + cg * 4];
        #pragma unroll
        for (int r = 0; r < 4; r++) {
            unsigned long long xp = pack2(Xs[(rg * 4 + r) * 65 + k]);
            fma2(acc[r][0], xp, w.x);
            fma2(acc[r][1], xp, w.y);
        }
    }

    #pragma unroll
    for (int r = 0; r < 4; r++) {
        int row = rowBase + rg * 4 + r;
        if (row < N_NODES) {
            float s = g_dinv[row];
            float2 p0 = unpack2(acc[r][0]), p1 = unpack2(acc[r][1]);
            float4 o = make_float4(p0.x*s, p0.y*s, p1.x*s, p1.y*s);
            *(float4*)&g_h2s[(long long)row * CDIM + cg * 4] = o;
        }
    }
}

// ---------- agg2 + bias + log_softmax fused: warp per node, write final out ----
__global__ __launch_bounds__(256) void k_agg2(const float* __restrict__ b2,
                                              float* __restrict__ out) {
    int warp = (blockIdx.x * blockDim.x + threadIdx.x) >> 5;
    if (warp >= N_NODES) return;
    int lane = threadIdx.x & 31;
    int start = g_start[warp];
    int cnt   = g_count[warp];

    const float* self = &g_h2s[(long long)warp * CDIM];
    float acc0 = self[lane];
    float acc1 = (lane < 8) ? self[32 + lane] : 0.f;

    for (int b = 0; b < cnt; b += 32) {
        int nb = min(32, cnt - b);
        int s = (b + lane < cnt) ? g_srcs[start + b + lane] : 0;
        #pragma unroll 4
        for (int j = 0; j < nb; j++) {
            int sj = __shfl_sync(0xFFFFFFFFu, s, j);
            const float* rp = &g_h2s[(long long)sj * CDIM];
            acc0 += rp[lane];
            if (lane < 8) acc1 += rp[32 + lane];
        }
    }

    float s  = g_dinv[warp];
    float a0 = s * acc0 + b2[lane];
    float a1 = (lane < 8) ? (s * acc1 + b2[32 + lane]) : -3.4e38f;
    float m  = fmaxf(a0, a1);
    #pragma unroll
    for (int o = 16; o; o >>= 1) m = fmaxf(m, __shfl_xor_sync(0xFFFFFFFFu, m, o));
    float es = expf(a0 - m) + ((lane < 8) ? expf(a1 - m) : 0.f);
    #pragma unroll
    for (int o = 16; o; o >>= 1) es += __shfl_xor_sync(0xFFFFFFFFu, es, o);
    float l = m + logf(es);
    float* op = &out[(long long)warp * CDIM];
    op[lane] = a0 - l;
    if (lane < 8) op[32 + lane] = a1 - l;
}

// ---------------------------------------------------------------------------
extern "C" void kernel_launch(void* const* d_in, const int* in_sizes, int n_in,
                              void* d_out, int out_size) {
    const float* x  = (const float*)d_in[0];
    const int*   ei = (const int*)  d_in[1];
    const float* W1 = (const float*)d_in[2];
    const float* b1 = (const float*)d_in[3];
    const float* W2 = (const float*)d_in[4];
    const float* b2 = (const float*)d_in[5];
    float* out = (float*)d_out;
    const int E = in_sizes[1] / 2;

    k_zero <<<(N_NODES + 255) / 256, 256>>>();
    k_count<<<(E + 255) / 256, 256>>>(ei, E);
    k_scan <<<1, 1024>>>();
    k_place<<<(E + 255) / 256, 256>>>(ei, E);

    k_gemm1<<<(N_NODES + 127) / 128, 256>>>(x, W1);
    k_agg1 <<<(N_NODES * 32 + 255) / 256, 256>>>();
    k_gemm2<<<(N_NODES + 127) / 128, 320>>>(W2, b1);
    k_agg2 <<<(N_NODES * 32 + 255) / 256, 256>>>(b2, out);
}

// round 3
// speedup vs baseline: 1.5153x; 1.5153x over previous
#include <cuda_runtime.h>

#define N_NODES 100000
#define F_IN    128
#define HDIM    64
#define CDIM    40

// ---- scratch (device globals: no allocation allowed) ----
__device__ __align__(256) int   g_cnt [N_NODES];
__device__ __align__(256) float g_dinv[N_NODES];
__device__ __align__(256) float g_h1s [N_NODES * HDIM];   // (x@W1)*dinv[row]
__device__ __align__(256) float g_agg1[N_NODES * HDIM];   // init=self, += h1s[src]
__device__ __align__(256) float g_h2s [N_NODES * CDIM];
__device__ __align__(256) float g_agg2[N_NODES * CDIM];

// ---- packed f32x2 helpers (ptxas never emits FFMA2 from C++; PTX-only) ----
__device__ __forceinline__ unsigned long long pack2(float x) {
    unsigned long long r;
    asm("mov.b64 %0, {%1, %1};" : "=l"(r) : "f"(x));
    return r;
}
__device__ __forceinline__ void fma2(unsigned long long& d,
                                     unsigned long long a, unsigned long long b) {
    asm("fma.rn.f32x2 %0, %1, %2, %3;" : "=l"(d) : "l"(a), "l"(b), "l"(d));
}
__device__ __forceinline__ float2 unpack2(unsigned long long v) {
    float2 f;
    asm("mov.b64 {%0, %1}, %2;" : "=f"(f.x), "=f"(f.y) : "l"(v));
    return f;
}

// ---------------------------------------------------------------- degree ----
__global__ void k_zero() {
    int i = blockIdx.x * blockDim.x + threadIdx.x;
    if (i < N_NODES) g_cnt[i] = 0;
}

__global__ void k_count(const int* __restrict__ ei, int E) {
    int e = blockIdx.x * blockDim.x + threadIdx.x;
    if (e >= E) return;
    int d = ei[E + e];
    if ((unsigned)d < (unsigned)N_NODES) atomicAdd(&g_cnt[d], 1);
}

__global__ void k_dinv() {
    int i = blockIdx.x * blockDim.x + threadIdx.x;
    if (i < N_NODES) g_dinv[i] = rsqrtf(1.0f + (float)g_cnt[i]);   // +1 self loop
}

// ------------------------------------------------ GEMM1: h1s = (x@W1)*dinv ----
// block 256 thr, tile 128 rows x 64 cols; thread: 4 rows x 8 cols (f32x2 x4)
__global__ __launch_bounds__(256, 2) void k_gemm1(const float* __restrict__ x,
                                                  const float* __restrict__ W1) {
    __shared__ float Ws[32 * 64];        // 8 KB
    __shared__ float Xs[128 * 33];       // 16.9 KB

    const int tid = threadIdx.x;
    const int cg  = tid & 7;             // cols cg*8 .. cg*8+7
    const int rg  = tid >> 3;            // rows rg*4 .. rg*4+3
    const int rowBase = blockIdx.x * 128;

    unsigned long long acc[4][4];
    #pragma unroll
    for (int r = 0; r < 4; r++)
        #pragma unroll
        for (int c = 0; c < 4; c++) acc[r][c] = 0ull;

    for (int k0 = 0; k0 < F_IN; k0 += 32) {
        {   // stage W chunk [32][64]
            int r = tid >> 3, c = (tid & 7) * 8;
            float4 a = *(const float4*)&W1[(k0 + r) * HDIM + c];
            float4 b = *(const float4*)&W1[(k0 + r) * HDIM + c + 4];
            *(float4*)&Ws[r * 64 + c]     = a;
            *(float4*)&Ws[r * 64 + c + 4] = b;
        }
        {   // stage X chunk [128][32], pad 33
            int r = tid >> 1, kk = (tid & 1) * 16;
            int row = rowBase + r;
            float* s = &Xs[r * 33 + kk];
            if (row < N_NODES) {
                const float* xp = &x[(long long)row * F_IN + k0 + kk];
                float4 a = *(const float4*)(xp);
                float4 b = *(const float4*)(xp + 4);
                float4 c = *(const float4*)(xp + 8);
                float4 d = *(const float4*)(xp + 12);
                s[0]=a.x; s[1]=a.y; s[2]=a.z; s[3]=a.w;
                s[4]=b.x; s[5]=b.y; s[6]=b.z; s[7]=b.w;
                s[8]=c.x; s[9]=c.y; s[10]=c.z; s[11]=c.w;
                s[12]=d.x; s[13]=d.y; s[14]=d.z; s[15]=d.w;
            } else {
                #pragma unroll
                for (int i = 0; i < 16; i++) s[i] = 0.f;
            }
        }
        __syncthreads();
        #pragma unroll
        for (int k = 0; k < 32; k++) {
            ulonglong2 wa = *(const ulonglong2*)&Ws[k * 64 + cg * 8];
            ulonglong2 wb = *(const ulonglong2*)&Ws[k * 64 + cg * 8 + 4];
            #pragma unroll
            for (int r = 0; r < 4; r++) {
                unsigned long long xp = pack2(Xs[(rg * 4 + r) * 33 + k]);
                fma2(acc[r][0], xp, wa.x);
                fma2(acc[r][1], xp, wa.y);
                fma2(acc[r][2], xp, wb.x);
                fma2(acc[r][3], xp, wb.y);
            }
        }
        __syncthreads();
    }

    #pragma unroll
    for (int r = 0; r < 4; r++) {
        int row = rowBase + rg * 4 + r;
        if (row < N_NODES) {
            float s = g_dinv[row];
            float2 p0 = unpack2(acc[r][0]), p1 = unpack2(acc[r][1]);
            float2 p2 = unpack2(acc[r][2]), p3 = unpack2(acc[r][3]);
            float4 o0 = make_float4(p0.x*s, p0.y*s, p1.x*s, p1.y*s);
            float4 o1 = make_float4(p2.x*s, p2.y*s, p3.x*s, p3.y*s);
            float* d1 = &g_h1s [(long long)row * HDIM + cg * 8];
            float* d2 = &g_agg1[(long long)row * HDIM + cg * 8];
            *(float4*)(d1)     = o0;  *(float4*)(d1 + 4) = o1;
            *(float4*)(d2)     = o0;  *(float4*)(d2 + 4) = o1;   // self-loop init
        }
    }
}

// ------------------------------------------------ scatter1: agg1[dst] += h1s[src]
__global__ void k_scatter1(const int* __restrict__ ei, int E) {
    long long idx = (long long)blockIdx.x * blockDim.x + threadIdx.x;
    long long total = (long long)E * 16;          // 16 float4 chunks per edge
    if (idx >= total) return;
    int e = (int)(idx >> 4);
    int c = ((int)idx & 15) * 4;
    int s = ei[e], d = ei[E + e];
    if ((unsigned)s >= (unsigned)N_NODES || (unsigned)d >= (unsigned)N_NODES) return;
    float4 v = *(const float4*)&g_h1s[(long long)s * HDIM + c];
    float* p = &g_agg1[(long long)d * HDIM + c];
    asm volatile("red.global.add.v4.f32 [%0], {%1, %2, %3, %4};"
                 :: "l"(p), "f"(v.x), "f"(v.y), "f"(v.z), "f"(v.w) : "memory");
}

// ------------------ GEMM2: h2s = relu(dinv*agg1 + b1) @ W2 * dinv  (f32x2) ----
__global__ __launch_bounds__(320) void k_gemm2(const float* __restrict__ W2,
                                               const float* __restrict__ b1) {
    __shared__ float Ws[64 * 40];
    __shared__ float Xs[128 * 65];
    __shared__ float Bs[64];

    const int tid = threadIdx.x;
    const int cg  = tid % 10;            // cols cg*4 .. cg*4+3
    const int rg  = tid / 10;            // rows rg*4 .. rg*4+3
    const int rowBase = blockIdx.x * 128;

    for (int i = tid; i < 64 * 40; i += 320) Ws[i] = W2[i];
    if (tid < 64) Bs[tid] = b1[tid];
    __syncthreads();

    for (int i = tid; i < 128 * 64; i += 320) {
        int r = i >> 6, k = i & 63;
        int row = rowBase + r;
        float v = 0.f;
        if (row < N_NODES)
            v = fmaxf(g_dinv[row] * g_agg1[(long long)row * HDIM + k] + Bs[k], 0.f);
        Xs[r * 65 + k] = v;
    }
    __syncthreads();

    unsigned long long acc[4][2];
    #pragma unroll
    for (int r = 0; r < 4; r++) { acc[r][0] = 0ull; acc[r][1] = 0ull; }

    #pragma unroll 4
    for (int k = 0; k < 64; k++) {
        ulonglong2 w = *(const ulonglong2*)&Ws[k * 40 + cg * 4];
        #pragma unroll
        for (int r = 0; r < 4; r++) {
            unsigned long long xp = pack2(Xs[(rg * 4 + r) * 65 + k]);
            fma2(acc[r][0], xp, w.x);
            fma2(acc[r][1], xp, w.y);
        }
    }

    #pragma unroll
    for (int r = 0; r < 4; r++) {
        int row = rowBase + rg * 4 + r;
        if (row < N_NODES) {
            float s = g_dinv[row];
            float2 p0 = unpack2(acc[r][0]), p1 = unpack2(acc[r][1]);
            float4 o = make_float4(p0.x*s, p0.y*s, p1.x*s, p1.y*s);
            *(float4*)&g_h2s [(long long)row * CDIM + cg * 4] = o;
            *(float4*)&g_agg2[(long long)row * CDIM + cg * 4] = o;  // self-loop init
        }
    }
}

// ------------------------------------------------ scatter2: agg2[dst] += h2s[src]
__global__ void k_scatter2(const int* __restrict__ ei, int E) {
    long long idx = (long long)blockIdx.x * blockDim.x + threadIdx.x;
    long long total = (long long)E * 10;          // 10 float4 chunks per edge
    if (idx >= total) return;
    int e = (int)(idx / 10);
    int c = (int)(idx % 10) * 4;
    int s = ei[e], d = ei[E + e];
    if ((unsigned)s >= (unsigned)N_NODES || (unsigned)d >= (unsigned)N_NODES) return;
    float4 v = *(const float4*)&g_h2s[(long long)s * CDIM + c];
    float* p = &g_agg2[(long long)d * CDIM + c];
    asm volatile("red.global.add.v4.f32 [%0], {%1, %2, %3, %4};"
                 :: "l"(p), "f"(v.x), "f"(v.y), "f"(v.z), "f"(v.w) : "memory");
}

// -------------------------------------- final: out = log_softmax(dinv*agg2 + b2)
__global__ void k_final(const float* __restrict__ b2, float* __restrict__ out) {
    int gtid = blockIdx.x * blockDim.x + threadIdx.x;
    int row  = gtid >> 5;
    int lane = threadIdx.x & 31;
    if (row >= N_NODES) return;
    const float* rp = &g_agg2[(long long)row * CDIM];
    float s  = g_dinv[row];
    float a0 = s * rp[lane] + b2[lane];
    float a1 = (lane < 8) ? (s * rp[32 + lane] + b2[32 + lane]) : -3.4e38f;
    float m  = fmaxf(a0, a1);
    #pragma unroll
    for (int o = 16; o; o >>= 1) m = fmaxf(m, __shfl_xor_sync(0xFFFFFFFFu, m, o));
    float es = expf(a0 - m) + ((lane < 8) ? expf(a1 - m) : 0.f);
    #pragma unroll
    for (int o = 16; o; o >>= 1) es += __shfl_xor_sync(0xFFFFFFFFu, es, o);
    float l = m + logf(es);
    out[(long long)row * CDIM + lane] = a0 - l;
    if (lane < 8) out[(long long)row * CDIM + 32 + lane] = a1 - l;
}

// ---------------------------------------------------------------------------
extern "C" void kernel_launch(void* const* d_in, const int* in_sizes, int n_in,
                              void* d_out, int out_size) {
    const float* x  = (const float*)d_in[0];
    const int*   ei = (const int*)  d_in[1];
    const float* W1 = (const float*)d_in[2];
    const float* b1 = (const float*)d_in[3];
    const float* W2 = (const float*)d_in[4];
    const float* b2 = (const float*)d_in[5];
    float* out = (float*)d_out;
    const int E = in_sizes[1] / 2;

    k_zero <<<(N_NODES + 255) / 256, 256>>>();
    k_count<<<(E + 255) / 256, 256>>>(ei, E);
    k_dinv <<<(N_NODES + 255) / 256, 256>>>();

    k_gemm1<<<(N_NODES + 127) / 128, 256>>>(x, W1);
    {
        long long tot = (long long)E * 16;
        k_scatter1<<<(int)((tot + 255) / 256), 256>>>(ei, E);
    }
    k_gemm2<<<(N_NODES + 127) / 128, 320>>>(W2, b1);
    {
        long long tot = (long long)E * 10;
        k_scatter2<<<(int)((tot + 255) / 256), 256>>>(ei, E);
    }
    k_final<<<(N_NODES * 32 + 255) / 256, 256>>>(b2, out);
}

// round 4
// speedup vs baseline: 1.6535x; 1.0912x over previous
#include <cuda_runtime.h>

#define N_NODES 100000
#define F_IN    128
#define HDIM    64
#define CDIM    40

// ---- scratch (device globals: no allocation allowed) ----
__device__ __align__(256) int   g_cnt [N_NODES];
__device__ __align__(256) float g_dinv[N_NODES];
__device__ __align__(256) float g_h1s [N_NODES * HDIM];   // (x@W1)*dinv[row]
__device__ __align__(256) float g_agg1[N_NODES * HDIM];   // init=self, += h1s[src]
__device__ __align__(256) float g_h2s [N_NODES * CDIM];
__device__ __align__(256) float g_agg2[N_NODES * CDIM];

// ---------------------------------------------------------------- degree ----
__global__ void k_zero() {
    int i = blockIdx.x * blockDim.x + threadIdx.x;
    if (i < N_NODES) g_cnt[i] = 0;
}

__global__ void k_count(const int* __restrict__ ei, int E) {
    int e = blockIdx.x * blockDim.x + threadIdx.x;
    if (e >= E) return;
    int d = ei[E + e];
    if ((unsigned)d < (unsigned)N_NODES) atomicAdd(&g_cnt[d], 1);
}

__global__ void k_dinv() {
    int i = blockIdx.x * blockDim.x + threadIdx.x;
    if (i < N_NODES) g_dinv[i] = rsqrtf(1.0f + (float)g_cnt[i]);   // +1 self loop
}

// ------------------------------------------------ GEMM1: h1s = (x@W1)*dinv ----
// block 256 thr, tile 128 rows x 64 cols; thread: 8 rows x 4 cols, k-step 2
#define XPAD 36
__global__ __launch_bounds__(256, 3) void k_gemm1(const float* __restrict__ x,
                                                  const float* __restrict__ W1) {
    __shared__ float Ws[32 * 64];         // 8 KB
    __shared__ float Xs[128 * XPAD];      // 18.4 KB (pad 36: 16B-aligned rows)

    const int tid = threadIdx.x;
    const int cg  = tid & 15;             // cols cg*4 .. cg*4+3
    const int rg  = tid >> 4;             // rows rg*8 .. rg*8+7
    const int rowBase = blockIdx.x * 128;

    float4 acc[8];
    #pragma unroll
    for (int r = 0; r < 8; r++) acc[r] = make_float4(0.f, 0.f, 0.f, 0.f);

    for (int k0 = 0; k0 < F_IN; k0 += 32) {
        {   // stage W chunk [32][64]: 8 floats per thread
            int r = tid >> 3, c = (tid & 7) * 8;
            float4 a = *(const float4*)&W1[(k0 + r) * HDIM + c];
            float4 b = *(const float4*)&W1[(k0 + r) * HDIM + c + 4];
            *(float4*)&Ws[r * 64 + c]     = a;
            *(float4*)&Ws[r * 64 + c + 4] = b;
        }
        {   // stage X chunk [128][32] into padded rows: 16 floats per thread
            int r = tid >> 1, kk = (tid & 1) * 16;
            int row = rowBase + r;
            float* s = &Xs[r * XPAD + kk];
            if (row < N_NODES) {
                const float* xp = &x[(long long)row * F_IN + k0 + kk];
                float4 a = *(const float4*)(xp);
                float4 b = *(const float4*)(xp + 4);
                float4 c = *(const float4*)(xp + 8);
                float4 d = *(const float4*)(xp + 12);
                *(float4*)(s)      = a;
                *(float4*)(s + 4)  = b;
                *(float4*)(s + 8)  = c;
                *(float4*)(s + 12) = d;
            } else {
                *(float4*)(s)      = make_float4(0.f,0.f,0.f,0.f);
                *(float4*)(s + 4)  = make_float4(0.f,0.f,0.f,0.f);
                *(float4*)(s + 8)  = make_float4(0.f,0.f,0.f,0.f);
                *(float4*)(s + 12) = make_float4(0.f,0.f,0.f,0.f);
            }
        }
        __syncthreads();
        #pragma unroll
        for (int k = 0; k < 32; k += 2) {
            float4 w0 = *(const float4*)&Ws[k * 64 + cg * 4];
            float4 w1 = *(const float4*)&Ws[(k + 1) * 64 + cg * 4];
            #pragma unroll
            for (int r = 0; r < 8; r++) {
                float2 xv = *(const float2*)&Xs[(rg * 8 + r) * XPAD + k];
                acc[r].x += xv.x * w0.x; acc[r].y += xv.x * w0.y;
                acc[r].z += xv.x * w0.z; acc[r].w += xv.x * w0.w;
                acc[r].x += xv.y * w1.x; acc[r].y += xv.y * w1.y;
                acc[r].z += xv.y * w1.z; acc[r].w += xv.y * w1.w;
            }
        }
        __syncthreads();
    }

    #pragma unroll
    for (int r = 0; r < 8; r++) {
        int row = rowBase + rg * 8 + r;
        if (row < N_NODES) {
            float s = g_dinv[row];
            float4 o = make_float4(acc[r].x * s, acc[r].y * s,
                                   acc[r].z * s, acc[r].w * s);
            *(float4*)&g_h1s [(long long)row * HDIM + cg * 4] = o;
            *(float4*)&g_agg1[(long long)row * HDIM + cg * 4] = o;   // self-loop init
        }
    }
}

// ------------------------------------------------ scatter1: agg1[dst] += h1s[src]
__global__ void k_scatter1(const int* __restrict__ ei, int E) {
    long long idx = (long long)blockIdx.x * blockDim.x + threadIdx.x;
    long long total = (long long)E * 16;          // 16 float4 chunks per edge
    if (idx >= total) return;
    int e = (int)(idx >> 4);
    int c = ((int)idx & 15) * 4;
    int s = ei[e], d = ei[E + e];
    if ((unsigned)s >= (unsigned)N_NODES || (unsigned)d >= (unsigned)N_NODES) return;
    float4 v = *(const float4*)&g_h1s[(long long)s * HDIM + c];
    float* p = &g_agg1[(long long)d * HDIM + c];
    asm volatile("red.global.add.v4.f32 [%0], {%1, %2, %3, %4};"
                 :: "l"(p), "f"(v.x), "f"(v.y), "f"(v.z), "f"(v.w) : "memory");
}

// --------------------------- GEMM2: h2s = relu(dinv*agg1 + b1) @ W2 * dinv ----
// block 320 thr, tile 128 rows x 40 cols; thread: 4 rows x 4 cols
__global__ __launch_bounds__(320) void k_gemm2(const float* __restrict__ W2,
                                               const float* __restrict__ b1) {
    __shared__ float Ws[64 * 40];        // 10.2 KB
    __shared__ float Xs[128 * 65];       // 33.3 KB (padded)
    __shared__ float Bs[64];

    const int tid = threadIdx.x;
    const int cg  = tid % 10;            // cols cg*4 .. cg*4+3
    const int rg  = tid / 10;            // rows rg*4 .. rg*4+3
    const int rowBase = blockIdx.x * 128;

    for (int i = tid; i < 64 * 40; i += 320) Ws[i] = W2[i];
    if (tid < 64) Bs[tid] = b1[tid];
    __syncthreads();

    for (int i = tid; i < 128 * 64; i += 320) {
        int r = i >> 6, k = i & 63;
        int row = rowBase + r;
        float v = 0.f;
        if (row < N_NODES)
            v = fmaxf(g_dinv[row] * g_agg1[(long long)row * HDIM + k] + Bs[k], 0.f);
        Xs[r * 65 + k] = v;
    }
    __syncthreads();

    float4 acc[4];
    #pragma unroll
    for (int r = 0; r < 4; r++) acc[r] = make_float4(0.f, 0.f, 0.f, 0.f);

    #pragma unroll 4
    for (int k = 0; k < 64; k++) {
        float4 w = *(const float4*)&Ws[k * 40 + cg * 4];
        #pragma unroll
        for (int r = 0; r < 4; r++) {
            float xv = Xs[(rg * 4 + r) * 65 + k];
            acc[r].x += xv * w.x; acc[r].y += xv * w.y;
            acc[r].z += xv * w.z; acc[r].w += xv * w.w;
        }
    }

    #pragma unroll
    for (int r = 0; r < 4; r++) {
        int row = rowBase + rg * 4 + r;
        if (row < N_NODES) {
            float s = g_dinv[row];
            float4 o = make_float4(acc[r].x * s, acc[r].y * s,
                                   acc[r].z * s, acc[r].w * s);
            *(float4*)&g_h2s [(long long)row * CDIM + cg * 4] = o;
            *(float4*)&g_agg2[(long long)row * CDIM + cg * 4] = o;  // self-loop init
        }
    }
}

// ------------------------------------------------ scatter2: agg2[dst] += h2s[src]
__global__ void k_scatter2(const int* __restrict__ ei, int E) {
    long long idx = (long long)blockIdx.x * blockDim.x + threadIdx.x;
    long long total = (long long)E * 10;          // 10 float4 chunks per edge
    if (idx >= total) return;
    int e = (int)(idx / 10);
    int c = (int)(idx % 10) * 4;
    int s = ei[e], d = ei[E + e];
    if ((unsigned)s >= (unsigned)N_NODES || (unsigned)d >= (unsigned)N_NODES) return;
    float4 v = *(const float4*)&g_h2s[(long long)s * CDIM + c];
    float* p = &g_agg2[(long long)d * CDIM + c];
    asm volatile("red.global.add.v4.f32 [%0], {%1, %2, %3, %4};"
                 :: "l"(p), "f"(v.x), "f"(v.y), "f"(v.z), "f"(v.w) : "memory");
}

// -------------------------------------- final: out = log_softmax(dinv*agg2 + b2)
__global__ void k_final(const float* __restrict__ b2, float* __restrict__ out) {
    int gtid = blockIdx.x * blockDim.x + threadIdx.x;
    int row  = gtid >> 5;
    int lane = threadIdx.x & 31;
    if (row >= N_NODES) return;
    const float* rp = &g_agg2[(long long)row * CDIM];
    float s  = g_dinv[row];
    float a0 = s * rp[lane] + b2[lane];
    float a1 = (lane < 8) ? (s * rp[32 + lane] + b2[32 + lane]) : -3.4e38f;
    float m  = fmaxf(a0, a1);
    #pragma unroll
    for (int o = 16; o; o >>= 1) m = fmaxf(m, __shfl_xor_sync(0xFFFFFFFFu, m, o));
    float es = expf(a0 - m) + ((lane < 8) ? expf(a1 - m) : 0.f);
    #pragma unroll
    for (int o = 16; o; o >>= 1) es += __shfl_xor_sync(0xFFFFFFFFu, es, o);
    float l = m + logf(es);
    out[(long long)row * CDIM + lane] = a0 - l;
    if (lane < 8) out[(long long)row * CDIM + 32 + lane] = a1 - l;
}

// ---------------------------------------------------------------------------
extern "C" void kernel_launch(void* const* d_in, const int* in_sizes, int n_in,
                              void* d_out, int out_size) {
    const float* x  = (const float*)d_in[0];
    const int*   ei = (const int*)  d_in[1];
    const float* W1 = (const float*)d_in[2];
    const float* b1 = (const float*)d_in[3];
    const float* W2 = (const float*)d_in[4];
    const float* b2 = (const float*)d_in[5];
    float* out = (float*)d_out;
    const int E = in_sizes[1] / 2;

    k_zero <<<(N_NODES + 255) / 256, 256>>>();
    k_count<<<(E + 255) / 256, 256>>>(ei, E);
    k_dinv <<<(N_NODES + 255) / 256, 256>>>();

    k_gemm1<<<(N_NODES + 127) / 128, 256>>>(x, W1);
    {
        long long tot = (long long)E * 16;
        k_scatter1<<<(int)((tot + 255) / 256), 256>>>(ei, E);
    }
    k_gemm2<<<(N_NODES + 127) / 128, 320>>>(W2, b1);
    {
        long long tot = (long long)E * 10;
        k_scatter2<<<(int)((tot + 255) / 256), 256>>>(ei, E);
    }
    k_final<<<(N_NODES * 32 + 255) / 256, 256>>>(b2, out);
}